// round 8
// baseline (speedup 1.0000x reference)
#include <cuda_runtime.h>
#include <cstdint>

#define NBLK 64
#define NTHR 256
#define HID  512
#define BB   32
#define TT   32
#define INF_ 397
#define NOUT 129

// logits: 32*32*129 = 132096, h: 32*512, c: 32*512
#define LOGITS_ELEMS 132096
#define HC_ELEMS     16384

// smem layout (floats):
//  sW   : [0, 16384)            W_hh slice: 8 warps x 4 gates x 512
//  sh   : [16384, 16384+20480)  h staging [512][32] (16384) / precompute: latT(8192)+chT(12288)
//  sred : [+0, +256)            8x32 cross-warp logits reduce
//  sidx : 32 ints
//  sE   : epoch base
#define SMEM_FLOATS (16384 + 20480 + 256 + 32 + 8)
#define SMEM_BYTES  (SMEM_FLOATS * 4)

__device__ float g_pre[TT * 2048 * BB];   // [t][row][b]
__device__ float g_h[HID * BB];           // h, [k][b]
__device__ float g_th[HID * BB];          // tanh(h), [k][b]
__device__ __align__(128) unsigned g_arrive;   // monotonic across launches
__device__ __align__(128) unsigned g_epoch;    // monotonic; read only at launch start

__device__ __forceinline__ float sigm(float x) { return 1.f / (1.f + __expf(-x)); }
__device__ __forceinline__ float tanh_p(float x) {
    float e = __expf(-2.f * fabsf(x));
    float r = (1.f - e) / (1.f + e);
    return copysignf(r, x);
}

// Direct-poll monotonic barrier (64 participants).
__device__ __forceinline__ void gbar(unsigned target) {
    __syncthreads();
    if (threadIdx.x == 0) {
        __threadfence();
        asm volatile("red.release.gpu.global.add.u32 [%0], 1;"
                     :: "l"(&g_arrive) : "memory");
        const unsigned want = target * NBLK;
        unsigned a;
        do {
            asm volatile("ld.acquire.gpu.global.u32 %0, [%1];"
                         : "=r"(a) : "l"(&g_arrive) : "memory");
        } while ((int)(a - want) < 0);
        if (blockIdx.x == 0) {
            asm volatile("red.release.gpu.global.add.u32 [%0], 1;"
                         :: "l"(&g_epoch) : "memory");
        }
        __threadfence();
    }
    __syncthreads();
}

__global__ void __launch_bounds__(NTHR, 1)
decoder_kernel(const float* __restrict__ chords, const float* __restrict__ latent,
               const float* __restrict__ W_ih, const float* __restrict__ W_hh,
               const float* __restrict__ b_ih, const float* __restrict__ b_hh,
               const float* __restrict__ W_lin, const float* __restrict__ b_lin,
               float* __restrict__ out, int out_size)
{
    extern __shared__ float smem[];
    float* sW   = smem;                    // 16384
    float* sh   = smem + 16384;            // 20480
    float* sred = smem + 16384 + 20480;    // 256
    int*   sidx = (int*)(sred + 256);      // 32
    unsigned* sE = (unsigned*)(sidx + 32);

    const int tid  = threadIdx.x;
    const int lane = tid & 31;
    const int wid  = tid >> 5;             // 0..7
    const int bid  = blockIdx.x;           // 0..63
    const int j    = (bid << 3) + wid;     // hidden unit owned by this warp (0..511)

    if (tid == 0) {
        unsigned e0;
        asm volatile("ld.acquire.gpu.global.u32 %0, [%1];"
                     : "=r"(e0) : "l"(&g_epoch) : "memory");
        sE[0] = e0;                        // stable epoch base for this launch
    }

    // ---- Stage W_hh rows (i,f,g,o for unit j) into smem: persists all 32 steps ----
    {
        float* dst = sW + wid * 2048;
        #pragma unroll
        for (int g = 0; g < 4; ++g) {
            const float* src = W_hh + (size_t)(g * HID + j) * HID;
            for (int k = (lane << 2); k < 512; k += 128)
                *(float4*)(dst + g * 512 + k) = *(const float4*)(src + k);
        }
    }
    // ---- Transpose latent -> sh[l][b] (8192 floats) ----
    for (int i = tid; i < BB * 256; i += NTHR) {
        int b = i >> 8, l = i & 255;
        sh[l * 32 + b] = latent[i];
    }
    // ---- Transpose chords -> sh[8192 + (t*12+c)*32 + b] (12288 floats) ----
    {
        float* sch = sh + 8192;
        for (int i = tid; i < BB * TT * 12; i += NTHR) {
            int b = i / 384, rem = i - b * 384;
            sch[rem * 32 + b] = chords[i];
        }
    }
    __syncthreads();

    // ---- Precompute g_pre[t][row][b] = b_ih + b_hh + latent.W_ih + chords(t).W_ih ----
    {
        const float* sch = sh + 8192;
        #pragma unroll
        for (int g = 0; g < 4; ++g) {
            const int row = g * HID + j;
            const float* wrow = W_ih + (size_t)row * INF_;
            float acc = __ldg(b_ih + row) + __ldg(b_hh + row);
            #pragma unroll 8
            for (int k = 0; k < 256; ++k)
                acc = fmaf(sh[k * 32 + lane], __ldg(wrow + k), acc);
            float wc[12];
            #pragma unroll
            for (int cc = 0; cc < 12; ++cc) wc[cc] = __ldg(wrow + 385 + cc);
            for (int t = 0; t < TT; ++t) {
                float z = acc;
                #pragma unroll
                for (int cc = 0; cc < 12; ++cc)
                    z = fmaf(sch[(t * 12 + cc) * 32 + lane], wc[cc], z);
                g_pre[((size_t)(t * 2048) + row) * 32 + lane] = z;
            }
        }
    }
    __syncthreads();
    const unsigned ep0 = sE[0];
    unsigned nbar = 0;

    const int r0 = j, r1 = HID + j, r2 = 2 * HID + j, r3 = 3 * HID + j;
    const float* w0 = sW + wid * 2048;
    const float* w1 = w0 + 512;
    const float* w2 = w0 + 1024;
    const float* w3 = w0 + 1536;

    float creg = 0.f;   // cell state c[b=lane][j], lives in a register all 32 steps

    for (int t = 0; t < TT; ++t) {
        // sh holds h(t-1), staged at the END of the previous step (pre-barB hoist).
        __syncthreads();   // drains the hoisted STS; orders sidx writes too

        const float* prebase = g_pre + (size_t)(t * 2048) * 32;
        float zi = prebase[r0 * 32 + lane];
        float zf = prebase[r1 * 32 + lane];
        float zg = prebase[r2 * 32 + lane];
        float zo = prebase[r3 * 32 + lane];

        if (t > 0) {
            // one-hot prev contribution: a single W_ih column gather per gate row
            const int pidx = sidx[lane];
            zi += __ldg(W_ih + (size_t)r0 * INF_ + 256 + pidx);
            zf += __ldg(W_ih + (size_t)r1 * INF_ + 256 + pidx);
            zg += __ldg(W_ih + (size_t)r2 * INF_ + 256 + pidx);
            zo += __ldg(W_ih + (size_t)r3 * INF_ + 256 + pidx);

            // recurrent dot: 4 gate rows x 512, h from smem, W from smem (broadcast)
            float a0=0.f,b0v=0.f,a1=0.f,b1v=0.f,a2=0.f,b2v=0.f,a3=0.f,b3v=0.f;
            #pragma unroll 2
            for (int k = 0; k < 512; k += 4) {
                float4 W0 = *(const float4*)(w0 + k);
                float4 W1 = *(const float4*)(w1 + k);
                float4 W2 = *(const float4*)(w2 + k);
                float4 W3 = *(const float4*)(w3 + k);
                float h0 = sh[k * 32 + lane];
                float h1 = sh[k * 32 + 32 + lane];
                float h2 = sh[k * 32 + 64 + lane];
                float h3 = sh[k * 32 + 96 + lane];
                a0 = fmaf(W0.x, h0, a0); b0v = fmaf(W0.y, h1, b0v);
                a0 = fmaf(W0.z, h2, a0); b0v = fmaf(W0.w, h3, b0v);
                a1 = fmaf(W1.x, h0, a1); b1v = fmaf(W1.y, h1, b1v);
                a1 = fmaf(W1.z, h2, a1); b1v = fmaf(W1.w, h3, b1v);
                a2 = fmaf(W2.x, h0, a2); b2v = fmaf(W2.y, h1, b2v);
                a2 = fmaf(W2.z, h2, a2); b2v = fmaf(W2.w, h3, b2v);
                a3 = fmaf(W3.x, h0, a3); b3v = fmaf(W3.y, h1, b3v);
                a3 = fmaf(W3.z, h2, a3); b3v = fmaf(W3.w, h3, b3v);
            }
            zi += a0 + b0v; zf += a1 + b1v; zg += a2 + b2v; zo += a3 + b3v;
        }

        const float gi = sigm(zi), gf = sigm(zf), gg = tanh_p(zg), go = sigm(zo);
        creg = gf * creg + gi * gg;
        const float hv = go * tanh_p(creg);
        const float th = tanh_p(hv);
        g_h[j * 32 + lane]  = hv;
        g_th[j * 32 + lane] = th;
        if (t == TT - 1 && out_size >= LOGITS_ELEMS + 2 * HC_ELEMS) {
            out[LOGITS_ELEMS + lane * HID + j]            = hv;
            out[LOGITS_ELEMS + HC_ELEMS + lane * HID + j] = creg;
        }

        gbar(ep0 + (++nbar));   // barA: h(t)/th(t) visible chip-wide

        // ---- logits: CTA half (warps 0-3 / 4-7) computes o = 2*bid + half.
        //      Same 4-warp x 128-k split and reduce order as before -> identical
        //      arithmetic per output column. CTA0 half0 additionally does o=128.
        {
            const int half = wid >> 2;       // 0 or 1
            const int kq   = wid & 3;        // k quarter within the half's team
            const int o    = bid * 2 + half; // 0..127
            {
                const float* wl  = W_lin + (size_t)o * HID + kq * 128;
                const float* thp = g_th + (kq * 128) * 32;
                float c0 = 0.f, c1 = 0.f, c2 = 0.f, c3 = 0.f;
                #pragma unroll
                for (int k = 0; k < 128; k += 4) {
                    c0 = fmaf(__ldcg(thp + (k + 0) * 32 + lane), __ldg(wl + k + 0), c0);
                    c1 = fmaf(__ldcg(thp + (k + 1) * 32 + lane), __ldg(wl + k + 1), c1);
                    c2 = fmaf(__ldcg(thp + (k + 2) * 32 + lane), __ldg(wl + k + 2), c2);
                    c3 = fmaf(__ldcg(thp + (k + 3) * 32 + lane), __ldg(wl + k + 3), c3);
                }
                sred[wid * 32 + lane] = (c0 + c1) + (c2 + c3);
            }
            __syncthreads();
            if (kq == 0) {   // wid 0 and wid 4 reduce their half's 4 partials
                const int base = half * 4;
                float tot = sred[(base + 0) * 32 + lane] + sred[(base + 1) * 32 + lane]
                          + sred[(base + 2) * 32 + lane] + sred[(base + 3) * 32 + lane]
                          + __ldg(b_lin + o);
                out[lane * (TT * NOUT) + t * NOUT + o] = tot;
            }
            __syncthreads();
            // extra column o=128 on CTA0 warps 0-3 (same scheme)
            if (bid == 0 && half == 0) {
                const float* wl  = W_lin + (size_t)128 * HID + kq * 128;
                const float* thp = g_th + (kq * 128) * 32;
                float c0 = 0.f, c1 = 0.f, c2 = 0.f, c3 = 0.f;
                #pragma unroll
                for (int k = 0; k < 128; k += 4) {
                    c0 = fmaf(__ldcg(thp + (k + 0) * 32 + lane), __ldg(wl + k + 0), c0);
                    c1 = fmaf(__ldcg(thp + (k + 1) * 32 + lane), __ldg(wl + k + 1), c1);
                    c2 = fmaf(__ldcg(thp + (k + 2) * 32 + lane), __ldg(wl + k + 2), c2);
                    c3 = fmaf(__ldcg(thp + (k + 3) * 32 + lane), __ldg(wl + k + 3), c3);
                }
                sred[wid * 32 + lane] = (c0 + c1) + (c2 + c3);
            }
            __syncthreads();
            if (bid == 0 && wid == 0) {
                float tot = sred[lane] + sred[32 + lane] + sred[64 + lane]
                          + sred[96 + lane] + __ldg(b_lin + 128);
                out[lane * (TT * NOUT) + t * NOUT + 128] = tot;
            }
        }

        if (t < TT - 1) {
            // ---- HOISTED stage of h(t) for step t+1, issued BEFORE barB ----
            // g_h holds h(t) stably from barA(t) until some CTA passes barB(t);
            // barB can't complete before this CTA arrives -> race-free, latency
            // overlaps the barB wait + argmax.
            {
                const float4* src4 = (const float4*)g_h;
                float4* dst4 = (float4*)sh;
                #pragma unroll 4
                for (int i = tid; i < HID * BB / 4; i += NTHR) dst4[i] = __ldcg(src4 + i);
            }

            gbar(ep0 + (++nbar));   // barB: logits visible chip-wide

            // parallel per-CTA argmax on warps 0-3 (identical to prior rounds:
            // first-max with strict-> + index tie-break == jnp.argmax)
            if (wid < 4) {
                const int b  = (wid << 3) + (lane >> 2);
                const int og = lane & 3;
                const float* lp = out + b * (TT * NOUT) + t * NOUT;
                float best = -3.4e38f; int bix = 0x7fffffff;
                for (int o = og; o < NOUT; o += 4) {
                    float v = __ldcg(lp + o);
                    if (v > best) { best = v; bix = o; }
                }
                #pragma unroll
                for (int off = 1; off <= 2; off <<= 1) {
                    float v = __shfl_xor_sync(0xffffffffu, best, off);
                    int   x = __shfl_xor_sync(0xffffffffu, bix,  off);
                    if (v > best || (v == best && x < bix)) { best = v; bix = x; }
                }
                if (og == 0) sidx[b] = bix;
            }
            // loop-top __syncthreads orders the staged sh + sidx before use
        }
    }
}

extern "C" void kernel_launch(void* const* d_in, const int* in_sizes, int n_in,
                              void* d_out, int out_size) {
    // Resolve inputs by element count (order-robust; b_ih/b_hh are interchangeable
    // since only their sum is used).
    const int want[8] = {12288, 8192, 813056, 1048576, 2048, 2048, 66048, 129};
    const float* p[8] = {nullptr, nullptr, nullptr, nullptr, nullptr, nullptr, nullptr, nullptr};
    bool used[64] = {false};
    for (int w = 0; w < 8; ++w) {
        for (int i = 0; i < n_in && i < 64; ++i) {
            if (!used[i] && in_sizes[i] == want[w]) {
                p[w] = (const float*)d_in[i];
                used[i] = true;
                break;
            }
        }
    }
    cudaFuncSetAttribute(decoder_kernel, cudaFuncAttributeMaxDynamicSharedMemorySize, SMEM_BYTES);
    decoder_kernel<<<NBLK, NTHR, SMEM_BYTES>>>(p[0], p[1], p[2], p[3], p[4], p[5], p[6], p[7],
                                               (float*)d_out, out_size);
}

// round 9
// speedup vs baseline: 1.0962x; 1.0962x over previous
#include <cuda_runtime.h>
#include <cstdint>

#define NGATE 128
#define NBLK  129
#define NTHR  128
#define HID   512
#define BB    32
#define TT    32
#define INF_  397
#define NOUT  129

// logits: 32*32*129 = 132096, h: 32*512, c: 32*512
#define LOGITS_ELEMS 132096
#define HC_ELEMS     16384

// smem layout (floats):
//  sW   : [0, 8192)            W_hh slice: 4 warps x 4 gates x 512
//  sh   : [8192, 8192+20480)   h staging (pair-packed, 16384) / precompute latT+chT
//  sred : [28672, 28800)       4x32 cross-warp logits reduce
//  sidx : [28800, 28832)       argmax indices (int)
//  sE   : [28832, 28840)
#define SMEM_FLOATS 28840
#define SMEM_BYTES  (SMEM_FLOATS * 4)

__device__ __align__(16) float g_pre[TT * 2048 * BB];   // [t][row][b]
__device__ __align__(16) float g_h[HID * BB];           // h, PAIR-PACKED [kp][b][2]
__device__ __align__(16) float g_th[HID * BB];          // tanh(h), [k][b]
__device__ __align__(128) unsigned g_arrive;   // monotonic across launches
__device__ __align__(128) unsigned g_epoch;    // monotonic; read only at launch start

__device__ __forceinline__ float sigm(float x) { return 1.f / (1.f + __expf(-x)); }
__device__ __forceinline__ float tanh_p(float x) {
    float e = __expf(-2.f * fabsf(x));
    float r = (1.f - e) / (1.f + e);
    return copysignf(r, x);
}

// f32x2 FMA with pure u64 carriers (each half is an independent fma.rn.f32 —
// bit-identical to the scalar fmaf it replaces).
__device__ __forceinline__ void ffma2u(unsigned long long& acc, unsigned long long w, unsigned long long h) {
    asm volatile("fma.rn.f32x2 %0, %1, %2, %0;" : "+l"(acc) : "l"(w), "l"(h));
}
__device__ __forceinline__ float2 unpack2(unsigned long long v) {
    float2 r; asm("mov.b64 {%0, %1}, %2;" : "=f"(r.x), "=f"(r.y) : "l"(v)); return r;
}

// Direct-poll monotonic barrier (129 participants).
__device__ __forceinline__ void gbar(unsigned target) {
    __syncthreads();
    if (threadIdx.x == 0) {
        __threadfence();
        asm volatile("red.release.gpu.global.add.u32 [%0], 1;"
                     :: "l"(&g_arrive) : "memory");
        const unsigned want = target * NBLK;
        unsigned a;
        do {
            asm volatile("ld.acquire.gpu.global.u32 %0, [%1];"
                         : "=r"(a) : "l"(&g_arrive) : "memory");
        } while ((int)(a - want) < 0);
        if (blockIdx.x == 0) {
            asm volatile("red.release.gpu.global.add.u32 [%0], 1;"
                         :: "l"(&g_epoch) : "memory");
        }
        __threadfence();
    }
    __syncthreads();
}

__global__ void __launch_bounds__(NTHR, 1)
decoder_kernel(const float* __restrict__ chords, const float* __restrict__ latent,
               const float* __restrict__ W_ih, const float* __restrict__ W_hh,
               const float* __restrict__ b_ih, const float* __restrict__ b_hh,
               const float* __restrict__ W_lin, const float* __restrict__ b_lin,
               float* __restrict__ out, int out_size)
{
    extern __shared__ float smem[];
    float* sW   = smem;                  // 8192
    float* sh   = smem + 8192;           // 20480
    float* sred = smem + 8192 + 20480;   // 128
    int*   sidx = (int*)(sred + 128);    // 32
    unsigned* sE = (unsigned*)(sidx + 32);

    const int tid  = threadIdx.x;
    const int lane = tid & 31;
    const int wid  = tid >> 5;
    const int bid  = blockIdx.x;         // 0..128; bid==128 is logits-only
    const int j    = (bid << 2) + wid;   // hidden unit (valid for bid < 128)

    if (tid == 0) {
        unsigned e0;
        asm volatile("ld.acquire.gpu.global.u32 %0, [%1];"
                     : "=r"(e0) : "l"(&g_epoch) : "memory");
        sE[0] = e0;                      // stable epoch base for this launch
    }

    if (bid < NGATE) {
        // ---- Stage W_hh rows (i,f,g,o for unit j) into smem ----
        {
            float* dst = sW + wid * 2048;
            #pragma unroll
            for (int g = 0; g < 4; ++g) {
                const float* src = W_hh + (size_t)(g * HID + j) * HID;
                for (int k = (lane << 2); k < 512; k += 128)
                    *(float4*)(dst + g * 512 + k) = *(const float4*)(src + k);
            }
        }
        // ---- Transpose latent -> sh[l][b] ----
        for (int i = tid; i < BB * 256; i += NTHR) {
            int b = i >> 8, l = i & 255;
            sh[l * 32 + b] = latent[i];
        }
        // ---- Transpose chords -> sh[8192 + (t*12+c)*32 + b] ----
        {
            float* sch = sh + 8192;
            for (int i = tid; i < BB * TT * 12; i += NTHR) {
                int b = i / 384, rem = i - b * 384;
                sch[rem * 32 + b] = chords[i];
            }
        }
        __syncthreads();

        // ---- Precompute g_pre[t][row][b] ----
        {
            const float* sch = sh + 8192;
            #pragma unroll
            for (int g = 0; g < 4; ++g) {
                const int row = g * HID + j;
                const float* wrow = W_ih + (size_t)row * INF_;
                float acc = __ldg(b_ih + row) + __ldg(b_hh + row);
                #pragma unroll 8
                for (int k = 0; k < 256; ++k)
                    acc = fmaf(sh[k * 32 + lane], __ldg(wrow + k), acc);
                float wc[12];
                #pragma unroll
                for (int cc = 0; cc < 12; ++cc) wc[cc] = __ldg(wrow + 385 + cc);
                for (int t = 0; t < TT; ++t) {
                    float z = acc;
                    #pragma unroll
                    for (int cc = 0; cc < 12; ++cc)
                        z = fmaf(sch[(t * 12 + cc) * 32 + lane], wc[cc], z);
                    g_pre[((size_t)(t * 2048) + row) * 32 + lane] = z;
                }
            }
        }
        __syncthreads();
    } else {
        __syncthreads();  // pair with sE publish
    }
    const unsigned ep0 = sE[0];
    unsigned nbar = 0;

    const int r0 = j, r1 = HID + j, r2 = 2 * HID + j, r3 = 3 * HID + j;
    const float* w0 = sW + wid * 2048;
    const float* w1 = w0 + 512;
    const float* w2 = w0 + 1024;
    const float* w3 = w0 + 1536;

    float creg = 0.f;

    for (int t = 0; t < TT; ++t) {
        if (bid < NGATE) {
            // sh holds h(t-1) pair-packed, staged pre-barB last step.
            __syncthreads();   // drains hoisted STS; orders sidx

            const float* prebase = g_pre + (size_t)(t * 2048) * 32;
            float zi = prebase[r0 * 32 + lane];
            float zf = prebase[r1 * 32 + lane];
            float zg = prebase[r2 * 32 + lane];
            float zo = prebase[r3 * 32 + lane];

            if (t > 0) {
                const int pidx = sidx[lane];
                zi += __ldg(W_ih + (size_t)r0 * INF_ + 256 + pidx);
                zf += __ldg(W_ih + (size_t)r1 * INF_ + 256 + pidx);
                zg += __ldg(W_ih + (size_t)r2 * INF_ + 256 + pidx);
                zo += __ldg(W_ih + (size_t)r3 * INF_ + 256 + pidx);

                // f32x2 recurrent dot. Accumulator halves: .x sums even k
                // (ascending), .y odd k — exactly the (a0, b0v) split of the
                // scalar version -> bit-identical partials.
                const unsigned long long* sh64 = (const unsigned long long*)sh;
                unsigned long long A0 = 0, A1 = 0, A2 = 0, A3 = 0;
                #pragma unroll 4
                for (int k = 0; k < 512; k += 4) {
                    const int kp = k >> 1;
                    unsigned long long h01 = sh64[kp * 32 + lane];        // h[k],h[k+1]
                    unsigned long long h23 = sh64[(kp + 1) * 32 + lane];  // h[k+2],h[k+3]
                    ulonglong2 Wa = *(const ulonglong2*)(w0 + k);
                    ulonglong2 Wb = *(const ulonglong2*)(w1 + k);
                    ulonglong2 Wc = *(const ulonglong2*)(w2 + k);
                    ulonglong2 Wd = *(const ulonglong2*)(w3 + k);
                    ffma2u(A0, Wa.x, h01); ffma2u(A1, Wb.x, h01);
                    ffma2u(A2, Wc.x, h01); ffma2u(A3, Wd.x, h01);
                    ffma2u(A0, Wa.y, h23); ffma2u(A1, Wb.y, h23);
                    ffma2u(A2, Wc.y, h23); ffma2u(A3, Wd.y, h23);
                }
                float2 u0 = unpack2(A0), u1 = unpack2(A1);
                float2 u2 = unpack2(A2), u3 = unpack2(A3);
                zi += u0.x + u0.y; zf += u1.x + u1.y;
                zg += u2.x + u2.y; zo += u3.x + u3.y;
            }

            const float gi = sigm(zi), gf = sigm(zf), gg = tanh_p(zg), go = sigm(zo);
            creg = gf * creg + gi * gg;
            const float hv = go * tanh_p(creg);
            const float th = tanh_p(hv);
            g_h[(j >> 1) * 64 + lane * 2 + (j & 1)] = hv;   // pair-packed [kp][b][2]
            g_th[j * 32 + lane] = th;                       // [k][b]
            if (t == TT - 1 && out_size >= LOGITS_ELEMS + 2 * HC_ELEMS) {
                out[LOGITS_ELEMS + lane * HID + j]            = hv;
                out[LOGITS_ELEMS + HC_ELEMS + lane * HID + j] = creg;
            }
        }

        gbar(ep0 + (++nbar));   // barA: h(t)/th(t) visible chip-wide

        // ---- logits: every CTA computes exactly one column o = bid ----
        {
            const int o = bid;
            const float* wl  = W_lin + (size_t)o * HID + wid * 128;
            const float* thp = g_th + (wid * 128) * 32;
            float c0 = 0.f, c1 = 0.f, c2 = 0.f, c3 = 0.f;
            #pragma unroll
            for (int k = 0; k < 128; k += 4) {
                c0 = fmaf(__ldcg(thp + (k + 0) * 32 + lane), __ldg(wl + k + 0), c0);
                c1 = fmaf(__ldcg(thp + (k + 1) * 32 + lane), __ldg(wl + k + 1), c1);
                c2 = fmaf(__ldcg(thp + (k + 2) * 32 + lane), __ldg(wl + k + 2), c2);
                c3 = fmaf(__ldcg(thp + (k + 3) * 32 + lane), __ldg(wl + k + 3), c3);
            }
            sred[wid * 32 + lane] = (c0 + c1) + (c2 + c3);
            __syncthreads();
            if (wid == 0) {
                float tot = sred[lane] + sred[32 + lane] + sred[64 + lane]
                          + sred[96 + lane] + __ldg(b_lin + o);
                out[lane * (TT * NOUT) + t * NOUT + o] = tot;
            }
            __syncthreads();
        }

        if (t < TT - 1) {
            if (bid < NGATE) {
                // HOISTED stage of h(t) (pair-packed copy) before barB —
                // race-free (barB can't complete before this CTA arrives),
                // latency overlaps barB wait + argmax.
                const float4* src4 = (const float4*)g_h;
                float4* dst4 = (float4*)sh;
                #pragma unroll 4
                for (int i = tid; i < HID * BB / 4; i += NTHR) dst4[i] = __ldcg(src4 + i);
            }

            gbar(ep0 + (++nbar));   // barB: logits visible chip-wide

            if (bid < NGATE) {
                // per-CTA argmax (first-max, == jnp.argmax)
                const int b  = (wid << 3) + (lane >> 2);
                const int og = lane & 3;
                const float* lp = out + b * (TT * NOUT) + t * NOUT;
                float best = -3.4e38f; int bix = 0x7fffffff;
                for (int o = og; o < NOUT; o += 4) {
                    float v = __ldcg(lp + o);
                    if (v > best) { best = v; bix = o; }
                }
                #pragma unroll
                for (int off = 1; off <= 2; off <<= 1) {
                    float v = __shfl_xor_sync(0xffffffffu, best, off);
                    int   x = __shfl_xor_sync(0xffffffffu, bix,  off);
                    if (v > best || (v == best && x < bix)) { best = v; bix = x; }
                }
                if (og == 0) sidx[b] = bix;
            }
        }
    }
}

extern "C" void kernel_launch(void* const* d_in, const int* in_sizes, int n_in,
                              void* d_out, int out_size) {
    const int want[8] = {12288, 8192, 813056, 1048576, 2048, 2048, 66048, 129};
    const float* p[8] = {nullptr, nullptr, nullptr, nullptr, nullptr, nullptr, nullptr, nullptr};
    bool used[64] = {false};
    for (int w = 0; w < 8; ++w) {
        for (int i = 0; i < n_in && i < 64; ++i) {
            if (!used[i] && in_sizes[i] == want[w]) {
                p[w] = (const float*)d_in[i];
                used[i] = true;
                break;
            }
        }
    }
    cudaFuncSetAttribute(decoder_kernel, cudaFuncAttributeMaxDynamicSharedMemorySize, SMEM_BYTES);
    decoder_kernel<<<NBLK, NTHR, SMEM_BYTES>>>(p[0], p[1], p[2], p[3], p[4], p[5], p[6], p[7],
                                               (float*)d_out, out_size);
}

// round 10
// speedup vs baseline: 1.3665x; 1.2466x over previous
#include <cuda_runtime.h>
#include <cstdint>

#define NGATE 128
#define NBLK  129
#define NTHR  128
#define HID   512
#define BB    32
#define TT    32
#define INF_  397
#define NOUT  129

#define LOGITS_ELEMS 132096
#define HC_ELEMS     16384

// smem floats: sW 8192 | sh 20480 | sred 128 | sE 8
#define SMEM_FLOATS 28840
#define SMEM_BYTES  (SMEM_FLOATS * 4)

__device__ __align__(16) float g_pre[TT * 2048 * BB];   // [t][row][b]
__device__ __align__(16) float g_h[HID * BB];           // h, PAIR-PACKED [kp][b][2]
__device__ __align__(16) float g_th[HID * BB];          // tanh(h), [k][b]
__device__ __align__(16) unsigned long long g_best[TT][BB];  // packed argmax keys
__device__ unsigned g_done[TT];                              // per-step publish counter
__device__ __align__(128) unsigned g_arrive;   // monotonic across launches
__device__ __align__(128) unsigned g_epoch;    // monotonic; read only at launch start

__device__ __forceinline__ float sigm(float x) { return 1.f / (1.f + __expf(-x)); }
__device__ __forceinline__ float tanh_p(float x) {
    float e = __expf(-2.f * fabsf(x));
    float r = (1.f - e) / (1.f + e);
    return copysignf(r, x);
}
__device__ __forceinline__ void ffma2u(unsigned long long& acc, unsigned long long w, unsigned long long h) {
    asm volatile("fma.rn.f32x2 %0, %1, %2, %0;" : "+l"(acc) : "l"(w), "l"(h));
}
__device__ __forceinline__ float2 unpack2(unsigned long long v) {
    float2 r; asm("mov.b64 {%0, %1}, %2;" : "=f"(r.x), "=f"(r.y) : "l"(v)); return r;
}
// monotone f32->u32 order embedding; key = (mkey << 32) | (255 - o):
// max key == max logit, ties -> smallest o == first-max == jnp.argmax.
__device__ __forceinline__ unsigned long long pack_key(float f, int o) {
    unsigned u = __float_as_uint(f);
    u = (u & 0x80000000u) ? ~u : (u | 0x80000000u);
    return (((unsigned long long)u) << 32) | (unsigned)(255 - o);
}

// Direct-poll monotonic barrier (129 participants). One per step now.
__device__ __forceinline__ void gbar(unsigned target) {
    __syncthreads();
    if (threadIdx.x == 0) {
        __threadfence();
        asm volatile("red.release.gpu.global.add.u32 [%0], 1;"
                     :: "l"(&g_arrive) : "memory");
        const unsigned want = target * NBLK;
        unsigned a;
        do {
            asm volatile("ld.acquire.gpu.global.u32 %0, [%1];"
                         : "=r"(a) : "l"(&g_arrive) : "memory");
        } while ((int)(a - want) < 0);
        if (blockIdx.x == 0) {
            asm volatile("red.release.gpu.global.add.u32 [%0], 1;"
                         :: "l"(&g_epoch) : "memory");
        }
        __threadfence();
    }
    __syncthreads();
}

__global__ void __launch_bounds__(NTHR, 1)
decoder_kernel(const float* __restrict__ chords, const float* __restrict__ latent,
               const float* __restrict__ W_ih, const float* __restrict__ W_hh,
               const float* __restrict__ b_ih, const float* __restrict__ b_hh,
               const float* __restrict__ W_lin, const float* __restrict__ b_lin,
               float* __restrict__ out, int out_size)
{
    extern __shared__ float smem[];
    float* sW   = smem;                  // 8192
    float* sh   = smem + 8192;           // 20480
    float* sred = smem + 8192 + 20480;   // 128
    unsigned* sE = (unsigned*)(sred + 128 + 32);

    const int tid  = threadIdx.x;
    const int lane = tid & 31;
    const int wid  = tid >> 5;
    const int bid  = blockIdx.x;         // 0..128; bid==128 is logits-only
    const int j    = (bid << 2) + wid;   // hidden unit (valid for bid < 128)

    if (tid == 0) {
        unsigned e0;
        asm volatile("ld.acquire.gpu.global.u32 %0, [%1];"
                     : "=r"(e0) : "l"(&g_epoch) : "memory");
        sE[0] = e0;
    }
    // per-launch reset of argmax state; ordered before any cross-CTA use by the
    // zeroing CTA's first barrier arrive (release) + readers' acquire.
    if (bid < TT) {
        if (tid < BB) g_best[bid][tid] = 0ull;
        if (tid == 0) g_done[bid] = 0u;
    }

    if (bid < NGATE) {
        // ---- Stage W_hh rows into smem ----
        {
            float* dst = sW + wid * 2048;
            #pragma unroll
            for (int g = 0; g < 4; ++g) {
                const float* src = W_hh + (size_t)(g * HID + j) * HID;
                for (int k = (lane << 2); k < 512; k += 128)
                    *(float4*)(dst + g * 512 + k) = *(const float4*)(src + k);
            }
        }
        for (int i = tid; i < BB * 256; i += NTHR) {
            int b = i >> 8, l = i & 255;
            sh[l * 32 + b] = latent[i];
        }
        {
            float* sch = sh + 8192;
            for (int i = tid; i < BB * TT * 12; i += NTHR) {
                int b = i / 384, rem = i - b * 384;
                sch[rem * 32 + b] = chords[i];
            }
        }
        __syncthreads();

        // ---- Precompute g_pre[t][row][b] ----
        {
            const float* sch = sh + 8192;
            #pragma unroll
            for (int g = 0; g < 4; ++g) {
                const int row = g * HID + j;
                const float* wrow = W_ih + (size_t)row * INF_;
                float acc = __ldg(b_ih + row) + __ldg(b_hh + row);
                #pragma unroll 8
                for (int k = 0; k < 256; ++k)
                    acc = fmaf(sh[k * 32 + lane], __ldg(wrow + k), acc);
                float wc[12];
                #pragma unroll
                for (int cc = 0; cc < 12; ++cc) wc[cc] = __ldg(wrow + 385 + cc);
                for (int t = 0; t < TT; ++t) {
                    float z = acc;
                    #pragma unroll
                    for (int cc = 0; cc < 12; ++cc)
                        z = fmaf(sch[(t * 12 + cc) * 32 + lane], wc[cc], z);
                    g_pre[((size_t)(t * 2048) + row) * 32 + lane] = z;
                }
            }
        }
        __syncthreads();
    } else {
        __syncthreads();
    }
    const unsigned ep0 = sE[0];

    const int r0 = j, r1 = HID + j, r2 = 2 * HID + j, r3 = 3 * HID + j;
    const float* w0 = sW + wid * 2048;
    const float* w1 = w0 + 512;
    const float* w2 = w0 + 1024;
    const float* w3 = w0 + 1536;

    float creg = 0.f;

    for (int t = 0; t < TT; ++t) {
        if (bid < NGATE) {
            __syncthreads();   // sh holds h(t-1); staging STS drained last iteration

            const float* prebase = g_pre + (size_t)(t * 2048) * 32;
            float zi = prebase[r0 * 32 + lane];
            float zf = prebase[r1 * 32 + lane];
            float zg = prebase[r2 * 32 + lane];
            float zo = prebase[r3 * 32 + lane];

            if (t > 0) {
                // ---- recurrent dot FIRST (doesn't need pidx) ----
                const unsigned long long* sh64 = (const unsigned long long*)sh;
                unsigned long long A0 = 0, A1 = 0, A2 = 0, A3 = 0;
                #pragma unroll 4
                for (int k = 0; k < 512; k += 4) {
                    const int kp = k >> 1;
                    unsigned long long h01 = sh64[kp * 32 + lane];
                    unsigned long long h23 = sh64[(kp + 1) * 32 + lane];
                    ulonglong2 Wa = *(const ulonglong2*)(w0 + k);
                    ulonglong2 Wb = *(const ulonglong2*)(w1 + k);
                    ulonglong2 Wc = *(const ulonglong2*)(w2 + k);
                    ulonglong2 Wd = *(const ulonglong2*)(w3 + k);
                    ffma2u(A0, Wa.x, h01); ffma2u(A1, Wb.x, h01);
                    ffma2u(A2, Wc.x, h01); ffma2u(A3, Wd.x, h01);
                    ffma2u(A0, Wa.y, h23); ffma2u(A1, Wb.y, h23);
                    ffma2u(A2, Wc.y, h23); ffma2u(A3, Wd.y, h23);
                }

                // ---- NOW wait for argmax(t-1) (normally already published) ----
                if (tid == 0) {
                    unsigned d;
                    do {
                        asm volatile("ld.acquire.gpu.global.u32 %0, [%1];"
                                     : "=r"(d) : "l"(&g_done[t - 1]) : "memory");
                    } while ((int)(d - NBLK) < 0);
                }
                __syncthreads();
                unsigned long long key;
                asm volatile("ld.global.cg.u64 %0, [%1];"
                             : "=l"(key) : "l"(&g_best[t - 1][lane]) : "memory");
                const int pidx = 255 - (int)(unsigned)(key & 0xffu);

                // same add order as R9: pre + col, then dot halves
                zi += __ldg(W_ih + (size_t)r0 * INF_ + 256 + pidx);
                zf += __ldg(W_ih + (size_t)r1 * INF_ + 256 + pidx);
                zg += __ldg(W_ih + (size_t)r2 * INF_ + 256 + pidx);
                zo += __ldg(W_ih + (size_t)r3 * INF_ + 256 + pidx);
                float2 u0 = unpack2(A0), u1 = unpack2(A1);
                float2 u2 = unpack2(A2), u3 = unpack2(A3);
                zi += u0.x + u0.y; zf += u1.x + u1.y;
                zg += u2.x + u2.y; zo += u3.x + u3.y;
            }

            const float gi = sigm(zi), gf = sigm(zf), gg = tanh_p(zg), go = sigm(zo);
            creg = gf * creg + gi * gg;
            const float hv = go * tanh_p(creg);
            const float th = tanh_p(hv);
            g_h[(j >> 1) * 64 + lane * 2 + (j & 1)] = hv;   // pair-packed
            g_th[j * 32 + lane] = th;                       // [k][b]
            if (t == TT - 1 && out_size >= LOGITS_ELEMS + 2 * HC_ELEMS) {
                out[LOGITS_ELEMS + lane * HID + j]            = hv;
                out[LOGITS_ELEMS + HC_ELEMS + lane * HID + j] = creg;
            }
        }

        gbar(ep0 + t + 1);   // the ONLY barrier per step: h(t)/th(t) visible

        // ---- stage h(t) for next step's dot (gate CTAs; overlaps logits) ----
        if (bid < NGATE && t < TT - 1) {
            const float4* src4 = (const float4*)g_h;
            float4* dst4 = (float4*)sh;
            #pragma unroll 4
            for (int i = tid; i < HID * BB / 4; i += NTHR) dst4[i] = __ldcg(src4 + i);
        }

        // ---- logits column o = bid (all CTAs; identical arithmetic to R9) ----
        {
            const int o = bid;
            const float* wl  = W_lin + (size_t)o * HID + wid * 128;
            const float* thp = g_th + (wid * 128) * 32;
            float c0 = 0.f, c1 = 0.f, c2 = 0.f, c3 = 0.f;
            #pragma unroll
            for (int k = 0; k < 128; k += 4) {
                c0 = fmaf(__ldcg(thp + (k + 0) * 32 + lane), __ldg(wl + k + 0), c0);
                c1 = fmaf(__ldcg(thp + (k + 1) * 32 + lane), __ldg(wl + k + 1), c1);
                c2 = fmaf(__ldcg(thp + (k + 2) * 32 + lane), __ldg(wl + k + 2), c2);
                c3 = fmaf(__ldcg(thp + (k + 3) * 32 + lane), __ldg(wl + k + 3), c3);
            }
            sred[wid * 32 + lane] = (c0 + c1) + (c2 + c3);
            __syncthreads();   // also drains the staging STS above
            if (wid == 0) {
                float tot = sred[lane] + sred[32 + lane] + sred[64 + lane]
                          + sred[96 + lane] + __ldg(b_lin + o);
                out[lane * (TT * NOUT) + t * NOUT + o] = tot;
                if (t < TT - 1) {
                    unsigned long long key = pack_key(tot, o);
                    asm volatile("red.relaxed.gpu.global.max.u64 [%0], %1;"
                                 :: "l"(&g_best[t][lane]), "l"(key) : "memory");
                }
            }
            __syncthreads();
            if (t < TT - 1 && tid == 0) {
                __threadfence();
                asm volatile("red.release.gpu.global.add.u32 [%0], 1;"
                             :: "l"(&g_done[t]) : "memory");
            }
        }
    }
}

extern "C" void kernel_launch(void* const* d_in, const int* in_sizes, int n_in,
                              void* d_out, int out_size) {
    const int want[8] = {12288, 8192, 813056, 1048576, 2048, 2048, 66048, 129};
    const float* p[8] = {nullptr, nullptr, nullptr, nullptr, nullptr, nullptr, nullptr, nullptr};
    bool used[64] = {false};
    for (int w = 0; w < 8; ++w) {
        for (int i = 0; i < n_in && i < 64; ++i) {
            if (!used[i] && in_sizes[i] == want[w]) {
                p[w] = (const float*)d_in[i];
                used[i] = true;
                break;
            }
        }
    }
    cudaFuncSetAttribute(decoder_kernel, cudaFuncAttributeMaxDynamicSharedMemorySize, SMEM_BYTES);
    decoder_kernel<<<NBLK, NTHR, SMEM_BYTES>>>(p[0], p[1], p[2], p[3], p[4], p[5], p[6], p[7],
                                               (float*)d_out, out_size);
}